// round 17
// baseline (speedup 1.0000x reference)
#include <cuda_runtime.h>
#include <math.h>

// Problem constants
constexpr int BATCH = 8;
constexpr int SEQ   = 2048;
constexpr int DIM   = 128;
constexpr int BC    = 64;    // keys per chunk
constexpr int NCHUNK = SEQ / BC;
constexpr int NQT64  = SEQ / 64;    // 64-row blob tiles per batch (32)
constexpr int NQT128 = SEQ / 128;   // attention CTAs per batch (16)
constexpr float SCALE   = 0.0883883476483184405f;    // 1/sqrt(128)
constexpr float LOG2E   = 1.4426950408889634074f;
constexpr float C1      = SCALE * LOG2E;             // score -> log2 domain
constexpr float BLOG    = -10000.0f * LOG2E;         // masked bias, log2 domain

// Fragment-major blobs, written directly by proj's epilogue.
__device__ float g_qf[BATCH * NQT64 * 8192];
__device__ float g_kf[BATCH * NCHUNK * 8192];
__device__ float g_vf[BATCH * NCHUNK * 8192];

__device__ __forceinline__ float to_tf32(float x) {
    unsigned u;
    asm("cvt.rna.tf32.f32 %0, %1;" : "=r"(u) : "f"(x));
    return __uint_as_float(u);
}

// m16n8k8 tf32 tensor-core mma (fp32 accumulate)
__device__ __forceinline__ void mma_tf32(float (&c)[4], const float (&a)[4],
                                         const float (&bf)[2])
{
    const unsigned* A = reinterpret_cast<const unsigned*>(a);
    const unsigned* B = reinterpret_cast<const unsigned*>(bf);
    asm volatile(
        "mma.sync.aligned.m16n8k8.row.col.f32.tf32.tf32.f32 "
        "{%0,%1,%2,%3}, {%4,%5,%6,%7}, {%8,%9}, {%0,%1,%2,%3};\n"
        : "+f"(c[0]), "+f"(c[1]), "+f"(c[2]), "+f"(c[3])
        : "r"(A[0]), "r"(A[1]), "r"(A[2]), "r"(A[3]), "r"(B[0]), "r"(B[1]));
}

__device__ __forceinline__ void cp16(void* smem, const void* g) {
    unsigned s = (unsigned)__cvta_generic_to_shared(smem);
    asm volatile("cp.async.cg.shared.global [%0], [%1], 16;\n"
                 :: "r"(s), "l"(g));
}
__device__ __forceinline__ void cp_commit() {
    asm volatile("cp.async.commit_group;\n");
}
template <int N>
__device__ __forceinline__ void cp_wait() {
    asm volatile("cp.async.wait_group %0;\n" :: "n"(N));
}

__device__ __forceinline__ float elu1(float x) {
    return x > 0.0f ? x : expm1f(x);
}

// ===========================================================================
// Kernel 1: fused QKV projection + fragment blob packing (round-15 format).
// ===========================================================================
constexpr int WSTRIDE    = 264;
constexpr int PSM_FLOATS = 128 * 132 + 128 * WSTRIDE;
constexpr int PSM_BYTES  = PSM_FLOATS * 4;

__global__ __launch_bounds__(256) void proj_kernel(
    const float* __restrict__ x,
    const float* __restrict__ Wq, const float* __restrict__ bq,
    const float* __restrict__ Wk, const float* __restrict__ bk,
    const float* __restrict__ Wv, const float* __restrict__ bv)
{
    extern __shared__ float psm[];
    float* const Xs  = psm;
    float* const Whl = psm + 128 * 132;

    const int t    = threadIdx.x;
    const int w    = t >> 5;
    const int lane = t & 31;
    const int qr   = lane >> 2;
    const int qc   = lane & 3;
    const int row0 = blockIdx.x * 128;
    const int bb    = row0 >> 11;
    const int cbase = (row0 & 2047) >> 6;

    {
        const float4* xg = (const float4*)(x + (size_t)row0 * DIM);
        #pragma unroll
        for (int i = 0; i < 16; ++i) {
            const int f = i * 256 + t;
            const int r = f >> 5, c4 = f & 31;
            *(float4*)(Xs + r * 132 + 4 * c4) = xg[f];
        }
    }

    #pragma unroll 1
    for (int gy = 0; gy < 3; ++gy) {
        const float* W    = gy == 0 ? Wq : (gy == 1 ? Wk : Wv);
        const float* bias = gy == 0 ? bq : (gy == 1 ? bk : bv);

        __syncthreads();
        {
            const float4* wg = (const float4*)W;
            #pragma unroll
            for (int i = 0; i < 16; ++i) {
                const int f = i * 256 + t;
                const int r = f >> 5, c4 = f & 31;
                const float4 v = wg[f];
                float hx = to_tf32(v.x), hy = to_tf32(v.y);
                float hz = to_tf32(v.z), hw = to_tf32(v.w);
                float* base = Whl + r * WSTRIDE + 8 * c4;
                ((float4*)base)[0] =
                    make_float4(hx, to_tf32(v.x - hx), hy, to_tf32(v.y - hy));
                ((float4*)base)[1] =
                    make_float4(hz, to_tf32(v.z - hz), hw, to_tf32(v.w - hw));
            }
        }
        __syncthreads();

        float C[16][4];
        #pragma unroll
        for (int n = 0; n < 16; ++n)
            #pragma unroll
            for (int i = 0; i < 4; ++i) C[n][i] = 0.0f;

        #pragma unroll
        for (int kt = 0; kt < 16; ++kt) {
            float ah[4], al[4];
            {
                const float* ap = Xs + (16 * w + qr) * 132 + 8 * kt + qc;
                float a0 = ap[0], a1 = ap[8 * 132], a2 = ap[4], a3 = ap[8 * 132 + 4];
                ah[0] = to_tf32(a0); al[0] = to_tf32(a0 - ah[0]);
                ah[1] = to_tf32(a1); al[1] = to_tf32(a1 - ah[1]);
                ah[2] = to_tf32(a2); al[2] = to_tf32(a2 - ah[2]);
                ah[3] = to_tf32(a3); al[3] = to_tf32(a3 - ah[3]);
            }
            const float* brow = Whl + (8 * kt + qc) * WSTRIDE + 2 * qr;
            #pragma unroll
            for (int n = 0; n < 16; ++n) {
                const float2 p0 = *(const float2*)(brow + 16 * n);
                const float2 p1 = *(const float2*)(brow + 16 * n + 4 * WSTRIDE);
                float bh[2] = {p0.x, p1.x};
                float bl[2] = {p0.y, p1.y};
                mma_tf32(C[n], ah, bh);
                mma_tf32(C[n], al, bh);
                mma_tf32(C[n], ah, bl);
            }
        }

        const int rA = 16 * w + qr;

        __syncthreads();
        float* const stage = Whl;
        #pragma unroll
        for (int n = 0; n < 16; ++n) {
            const int d0 = 8 * n + 2 * qc;
            const float b0 = bias[d0], b1 = bias[d0 + 1];
            float vv[4] = { to_tf32(C[n][0] + b0), to_tf32(C[n][1] + b1),
                            to_tf32(C[n][2] + b0), to_tf32(C[n][3] + b1) };
            #pragma unroll
            for (int e = 0; e < 4; ++e) {
                int addr;
                if (gy == 0) {
                    const int r   = rA + ((e >> 1) << 3);
                    const int cc  = 2 * qc + (e & 1);
                    const int tl  = r >> 6;
                    const int rl  = r & 63;
                    const int w2  = rl >> 4;
                    const int rr  = rl & 15;
                    const int ln2 = 4 * (rr & 7) + (cc & 3);
                    const int idx = ((cc >= 4) ? 2 : 0) + ((rr >= 8) ? 1 : 0);
                    addr = tl * 8192 + ((w2 * 16 + n) * 32 + ln2) * 4 + idx;
                } else {
                    const int kk = rA + ((e >> 1) << 3);
                    const int d  = d0 + (e & 1);
                    const int cs = kk >> 6;
                    const int kc = kk & 63;
                    if (gy == 1) {
                        const int li = 4 * (kc & 7) + (d & 3);
                        addr = cs * 8192 + (kc >> 3) * 1024 + li * 32 +
                               (((d >> 4) ^ (li & 7)) << 2) + ((d >> 2) & 3);
                    } else {
                        const int li = 4 * (d & 7) + (kc & 3);
                        addr = cs * 8192 + (d >> 3) * 512 + li * 16 +
                               ((((kc >> 4) & 3) ^ ((li >> 1) & 3)) << 2) +
                               ((kc >> 2) & 3);
                    }
                }
                stage[addr] = vv[e];
            }
        }
        __syncthreads();
        {
            float* gdst = gy == 0 ? g_qf : (gy == 1 ? g_kf : g_vf);
            float4* dst = (float4*)gdst + (size_t)(bb * NCHUNK + cbase) * 2048;
            const float4* src = (const float4*)stage;
            #pragma unroll
            for (int i = 0; i < 16; ++i)
                dst[i * 256 + t] = src[i * 256 + t];
        }
    }
}

// ===========================================================================
// Kernel 2: flash attention, 512 threads (16 warps), 1 CTA/SM, grid (16, 8).
// Warp w: rows 16*(w&7)..+15; half dh=w>>3 splits KEYS in QK (32 of 64) and
// OUTPUT DIMS in PV (64 of 128).  O regs/thread: 32 (was 128) -> 4 warps/SMSP.
// P exchanged between key-half partners (w <-> w^8) via named barrier rg+1.
// Double-buffered K/V via cp.async issued one chunk ahead.
// ===========================================================================
constexpr int QF   = 0;        // 16384 floats (two 64-row Q blobs)
constexpr int KB0  = 16384;    // 8192 floats
constexpr int KB1  = 24576;
constexpr int VB0  = 32768;
constexpr int VB1  = 40960;
constexpr int PSB  = 49152;    // Ps[128][68]
constexpr int PSTRIDE = 68;
constexpr int SMEM_FLOATS = PSB + 128 * PSTRIDE;    // 57856
constexpr int SMEM_BYTES  = SMEM_FLOATS * 4;        // 231424

__global__ __launch_bounds__(512, 1) void attn_kernel(
    const int* __restrict__ adj, float* __restrict__ out)
{
    extern __shared__ float sm[];

    const int t    = threadIdx.x;
    const int w    = t >> 5;
    const int lane = t & 31;
    const int qr   = lane >> 2;
    const int qc   = lane & 3;
    const int rg   = w & 7;      // row group: rows 16*rg .. +15
    const int dh   = w >> 3;     // half index (keys in QK, dims in PV)
    const int b    = blockIdx.y;
    const int qt   = blockIdx.x;

    // ---- Q tile: two 64-row blobs, straight cp.async copy ----
    {
        const float4* qs = (const float4*)g_qf + (size_t)(b * NQT64 + 2 * qt) * 2048;
        float4* qd = (float4*)(sm + QF);
        #pragma unroll
        for (int i = 0; i < 8; ++i) cp16(qd + i * 512 + t, qs + i * 512 + t);
        cp_commit();
    }
    // ---- chunk 0 K and V (one group) ----
    {
        const float4* ks = (const float4*)g_kf + (size_t)(b * NCHUNK) * 2048;
        const float4* vs = (const float4*)g_vf + (size_t)(b * NCHUNK) * 2048;
        float4* kd = (float4*)(sm + KB0);
        float4* vd = (float4*)(sm + VB0);
        #pragma unroll
        for (int i = 0; i < 4; ++i) cp16(kd + i * 512 + t, ks + i * 512 + t);
        #pragma unroll
        for (int i = 0; i < 4; ++i) cp16(vd + i * 512 + t, vs + i * 512 + t);
        cp_commit();
    }

    float O[8][4];
    #pragma unroll
    for (int n = 0; n < 8; ++n)
        #pragma unroll
        for (int i = 0; i < 4; ++i) O[n][i] = 0.0f;

    float l0 = 0.0f, l1 = 0.0f;   // per-thread, this key half

    // Q fragment sub-blob selectors (rows 16*rg)
    const float* qb0 = sm + QF + (rg >> 2) * 8192;
    const int    qw2 = rg & 3;

    const int row0 = qt * 128 + 16 * rg;
    const int* adj0 = adj + ((size_t)b * SEQ + row0 + qr) * SEQ;
    const int* adj1 = adj0 + 8 * SEQ;

    for (int c = 0; c < NCHUNK; ++c) {
        // ---- issue next chunk's K/V into the other buffer, then wait ----
        if (c + 1 < NCHUNK) {
            const int nb = (c + 1) & 1;
            const float4* ks = (const float4*)g_kf + (size_t)(b * NCHUNK + c + 1) * 2048;
            const float4* vs = (const float4*)g_vf + (size_t)(b * NCHUNK + c + 1) * 2048;
            float4* kd = (float4*)(sm + (nb ? KB1 : KB0));
            float4* vd = (float4*)(sm + (nb ? VB1 : VB0));
            #pragma unroll
            for (int i = 0; i < 4; ++i) cp16(kd + i * 512 + t, ks + i * 512 + t);
            #pragma unroll
            for (int i = 0; i < 4; ++i) cp16(vd + i * 512 + t, vs + i * 512 + t);
            cp_commit();
            cp_wait<1>();     // chunk c's K+V (and Q on c==0) complete
        } else {
            cp_wait<0>();
        }
        __syncthreads();

        const float* kb = sm + ((c & 1) ? KB1 : KB0);
        const float* vb = sm + ((c & 1) ? VB1 : VB0);
        const int key0 = c * BC;

        // ---- adjacency prefetch (this warp's key half) ----
        int2 A0[4], A1[4];
        #pragma unroll
        for (int jn = 0; jn < 4; ++jn) {
            const int col = key0 + 32 * dh + 8 * jn + 2 * qc;
            A0[jn] = __ldcs((const int2*)(adj0 + col));
            A1[jn] = __ldcs((const int2*)(adj1 + col));
        }

        // ---- S = Q K^T (1 row-tile x 4 key-tiles of this half) ----
        float S[4][4];
        #pragma unroll
        for (int j = 0; j < 4; ++j)
            #pragma unroll
            for (int i = 0; i < 4; ++i) S[j][i] = 0.0f;

        #pragma unroll
        for (int g = 0; g < 8; ++g) {
            float q0[4], q1[4];
            *(float4*)q0 = *(const float4*)(qb0 + ((qw2 * 16 + 2 * g)     * 32 + lane) * 4);
            *(float4*)q1 = *(const float4*)(qb0 + ((qw2 * 16 + 2 * g + 1) * 32 + lane) * 4);
            const int off = (g ^ (lane & 7)) << 2;
            #pragma unroll
            for (int jn = 0; jn < 4; ++jn) {
                const float4 kf = *(const float4*)(kb + (4 * dh + jn) * 1024 + lane * 32 + off);
                float bf0[2] = {kf.x, kf.y};
                float bf1[2] = {kf.z, kf.w};
                mma_tf32(S[jn], q0, bf0);
                mma_tf32(S[jn], q1, bf1);
            }
        }

        // ---- p = exp2(s*C1 + bias); accumulate l; store P ----
        #pragma unroll
        for (int jn = 0; jn < 4; ++jn) {
            float p0 = exp2f(fmaf(S[jn][0], C1, A0[jn].x ? 0.0f : BLOG));
            float p1 = exp2f(fmaf(S[jn][1], C1, A0[jn].y ? 0.0f : BLOG));
            float p2 = exp2f(fmaf(S[jn][2], C1, A1[jn].x ? 0.0f : BLOG));
            float p3 = exp2f(fmaf(S[jn][3], C1, A1[jn].y ? 0.0f : BLOG));
            l0 += p0 + p1;
            l1 += p2 + p3;
            const int prow = 16 * rg + qr;
            const int colp = 32 * dh + 8 * jn + 2 * qc;
            *(float2*)(sm + PSB + prow * PSTRIDE + colp) =
                make_float2(to_tf32(p0), to_tf32(p1));
            *(float2*)(sm + PSB + (prow + 8) * PSTRIDE + colp) =
                make_float2(to_tf32(p2), to_tf32(p3));
        }

        // ---- pair barrier: partner key-half's P visible (warps w, w^8) ----
        asm volatile("bar.sync %0, %1;" :: "r"(rg + 1), "r"(64) : "memory");

        // ---- O += P V (all 8 key-tiles, this warp's 8 dim-tiles) ----
        const float* pb = sm + PSB + (16 * rg + qr) * PSTRIDE;
        const int sw = (lane >> 1) & 3;
        #pragma unroll
        for (int jp = 0; jp < 4; ++jp) {
            float a0[4], a1[4];
            const int c0 = 8 * (2 * jp) + qc;
            const int c1 = 8 * (2 * jp + 1) + qc;
            a0[0] = pb[c0];
            a0[1] = pb[8 * PSTRIDE + c0];
            a0[2] = pb[c0 + 4];
            a0[3] = pb[8 * PSTRIDE + c0 + 4];
            a1[0] = pb[c1];
            a1[1] = pb[8 * PSTRIDE + c1];
            a1[2] = pb[c1 + 4];
            a1[3] = pb[8 * PSTRIDE + c1 + 4];
            #pragma unroll
            for (int n = 0; n < 8; ++n) {
                const int nn = 8 * dh + n;
                const float4 vf = *(const float4*)(vb + nn * 512 + lane * 16 + ((jp ^ sw) << 2));
                float bf0[2] = {vf.x, vf.y};
                float bf1[2] = {vf.z, vf.w};
                mma_tf32(O[n], a0, bf0);
                mma_tf32(O[n], a1, bf1);
            }
        }

        __syncthreads();   // all K/V/Ps reads done before next chunk's copies
    }

    // ---- epilogue: merge l key-half partials, normalize, ELU, store ----
    l0 += __shfl_xor_sync(0xffffffffu, l0, 1);
    l0 += __shfl_xor_sync(0xffffffffu, l0, 2);
    l1 += __shfl_xor_sync(0xffffffffu, l1, 1);
    l1 += __shfl_xor_sync(0xffffffffu, l1, 2);
    float* lp = sm + PSB;   // [2][128]; Ps area free now
    if (qc == 0) {
        lp[dh * 128 + 16 * rg + qr]     = l0;
        lp[dh * 128 + 16 * rg + qr + 8] = l1;
    }
    __syncthreads();
    {
        const int row = 16 * rg + qr;
        const float li0 = 1.0f / (lp[row]     + lp[128 + row]);
        const float li1 = 1.0f / (lp[row + 8] + lp[128 + row + 8]);
        float* out0 = out + ((size_t)b * SEQ + qt * 128 + row) * DIM + 64 * dh;
        float* out1 = out0 + 8 * DIM;
        #pragma unroll
        for (int n = 0; n < 8; ++n) {
            const int col = 8 * n + 2 * qc;
            *(float2*)(out0 + col) =
                make_float2(elu1(O[n][0] * li0), elu1(O[n][1] * li0));
            *(float2*)(out1 + col) =
                make_float2(elu1(O[n][2] * li1), elu1(O[n][3] * li1));
        }
    }
}

// ---------------------------------------------------------------------------
extern "C" void kernel_launch(void* const* d_in, const int* in_sizes, int n_in,
                              void* d_out, int out_size)
{
    const float* x   = (const float*)d_in[0];
    const int*   adj = (const int*)  d_in[1];
    const float* Wq  = (const float*)d_in[2];
    const float* bq  = (const float*)d_in[3];
    const float* Wk  = (const float*)d_in[4];
    const float* bk  = (const float*)d_in[5];
    const float* Wv  = (const float*)d_in[6];
    const float* bv  = (const float*)d_in[7];
    float* out = (float*)d_out;

    cudaFuncSetAttribute(proj_kernel,
                         cudaFuncAttributeMaxDynamicSharedMemorySize, PSM_BYTES);
    cudaFuncSetAttribute(attn_kernel,
                         cudaFuncAttributeMaxDynamicSharedMemorySize, SMEM_BYTES);

    proj_kernel<<<(BATCH * SEQ) / 128, 256, PSM_BYTES>>>(
        x, Wq, bq, Wk, bk, Wv, bv);

    attn_kernel<<<dim3(NQT128, BATCH), 512, SMEM_BYTES>>>(adj, out);
}